// round 1
// baseline (speedup 1.0000x reference)
#include <cuda_runtime.h>
#include <cuda_bf16.h>

#define NN 50000
#define NE 800000
#define DD 128
#define BN_EPS 1e-5f

// ---- scratch (static device globals; no allocation) ----
__device__ float g_h[NN * DD];     // GEMM output h = X @ W
__device__ float g_agg[NN * DD];   // aggregation buffer (reused both layers)
__device__ float g_x2[NN * DD];    // layer-1 activation output
__device__ float g_deg[NN];
__device__ float g_dinv[NN];
__device__ float g_stats[4 * DD];  // [sum1 | sumsq1 | sum2 | sumsq2]

// ------------------------------------------------------------------
// degree: deg[i] = 1 (self loop) + indegree; also zero the BN stats
// ------------------------------------------------------------------
__global__ void k_deg_init() {
    int i = blockIdx.x * 256 + threadIdx.x;
    if (i < NN) g_deg[i] = 1.0f;
    if (i < 4 * DD) g_stats[i] = 0.0f;
}

__global__ void k_deg_count(const int* __restrict__ dst) {
    int e = blockIdx.x * 256 + threadIdx.x;
    if (e < NE) atomicAdd(&g_deg[dst[e]], 1.0f);
}

__global__ void k_dinv() {
    int i = blockIdx.x * 256 + threadIdx.x;
    if (i < NN) g_dinv[i] = rsqrtf(g_deg[i]);
}

// ------------------------------------------------------------------
// SGEMM: H[r][c] = sum_k X[r][k] * W[k][c],  X:[NN,128], W:[128,128]
// block = 256 threads, 64 rows x 128 cols per block.
// dynamic smem: W full (64KB) + X tile (32KB) = 96KB.
// each thread: 8 rows x 4 cols register tile.
// ------------------------------------------------------------------
__global__ void k_gemm(const float* __restrict__ Xin,
                       const float* __restrict__ W,
                       int use_x2) {
    extern __shared__ float smem[];
    float* sW = smem;            // 128*128
    float* sX = smem + DD * DD;  // 64*128

    const float* X = use_x2 ? (const float*)g_x2 : Xin;
    float* H = g_h;

    int tid = threadIdx.x;
    int row0 = blockIdx.x * 64;

    // load W (16384 floats = 4096 float4)
    const float4* W4 = (const float4*)W;
    float4* sW4 = (float4*)sW;
    for (int i = tid; i < DD * DD / 4; i += 256) sW4[i] = W4[i];

    // load X tile (64 rows x 32 float4)
    for (int i = tid; i < 64 * 32; i += 256) {
        int r = i >> 5, c = i & 31;
        int gr = row0 + r;
        float4 v = make_float4(0.f, 0.f, 0.f, 0.f);
        if (gr < NN) v = ((const float4*)X)[gr * 32 + c];
        ((float4*)sX)[i] = v;
    }
    __syncthreads();

    int tx = tid & 31;   // column group: cols tx*4 .. tx*4+3
    int ty = tid >> 5;   // row group:    rows ty*8 .. ty*8+7

    float acc[8][4];
#pragma unroll
    for (int i = 0; i < 8; i++) {
        acc[i][0] = 0.f; acc[i][1] = 0.f; acc[i][2] = 0.f; acc[i][3] = 0.f;
    }

    const float* xbase = sX + (ty * 8) * DD;

    for (int k0 = 0; k0 < DD; k0 += 4) {
        float4 xv[8];
#pragma unroll
        for (int i = 0; i < 8; i++)
            xv[i] = *(const float4*)(xbase + i * DD + k0);
#pragma unroll
        for (int kk = 0; kk < 4; kk++) {
            float4 wv = *(const float4*)(sW + (k0 + kk) * DD + tx * 4);
#pragma unroll
            for (int i = 0; i < 8; i++) {
                float xs = (kk == 0) ? xv[i].x : (kk == 1) ? xv[i].y
                         : (kk == 2) ? xv[i].z : xv[i].w;
                acc[i][0] += xs * wv.x;
                acc[i][1] += xs * wv.y;
                acc[i][2] += xs * wv.z;
                acc[i][3] += xs * wv.w;
            }
        }
    }

#pragma unroll
    for (int i = 0; i < 8; i++) {
        int gr = row0 + ty * 8 + i;
        if (gr < NN) {
            float4 o = make_float4(acc[i][0], acc[i][1], acc[i][2], acc[i][3]);
            ((float4*)H)[gr * 32 + tx] = o;
        }
    }
}

// ------------------------------------------------------------------
// init aggregation: agg[i][c] = b[c] + h[i][c] * dinv[i]^2  (self loop fused)
// ------------------------------------------------------------------
__global__ void k_agg_init(const float* __restrict__ b) {
    int idx = blockIdx.x * 256 + threadIdx.x;  // over NN*32 float4
    if (idx >= NN * 32) return;
    int node = idx >> 5, c = idx & 31;
    float di = g_dinv[node];
    float w = di * di;
    float4 hv = ((const float4*)g_h)[idx];
    float4 bv = ((const float4*)b)[c];
    float4 o = make_float4(bv.x + hv.x * w, bv.y + hv.y * w,
                           bv.z + hv.z * w, bv.w + hv.w * w);
    ((float4*)g_agg)[idx] = o;
}

// ------------------------------------------------------------------
// edge scatter: one warp per edge, lane handles one float4 (16B) of the row.
// agg[dst] += h[src] * dinv[src]*dinv[dst]   via red.global.add.v4.f32
// ------------------------------------------------------------------
__global__ void k_scatter(const int* __restrict__ src,
                          const int* __restrict__ dst) {
    int e = blockIdx.x * 8 + (threadIdx.x >> 5);
    if (e >= NE) return;
    int lane = threadIdx.x & 31;
    int s = src[e];
    int d = dst[e];
    float w = g_dinv[s] * g_dinv[d];
    float4 v = ((const float4*)g_h)[s * 32 + lane];
    v.x *= w; v.y *= w; v.z *= w; v.w *= w;
    float* p = g_agg + (size_t)d * DD + lane * 4;
    asm volatile("red.global.add.v4.f32 [%0], {%1,%2,%3,%4};"
                 :: "l"(p), "f"(v.x), "f"(v.y), "f"(v.z), "f"(v.w)
                 : "memory");
}

// ------------------------------------------------------------------
// BN column statistics: per-block partial sums over 256 rows -> atomic add
// ------------------------------------------------------------------
__global__ void k_stats(int off) {
    int c = threadIdx.x & 127;
    int rr = threadIdx.x >> 7;  // 0 or 1
    int r0 = blockIdx.x * 256;
    int rend = min(r0 + 256, NN);
    float s = 0.f, q = 0.f;
    for (int r = r0 + rr; r < rend; r += 2) {
        float v = g_agg[r * DD + c];
        s += v;
        q += v * v;
    }
    atomicAdd(&g_stats[off + c], s);
    atomicAdd(&g_stats[off + DD + c], q);
}

// ------------------------------------------------------------------
// BN apply + PReLU: out = prelu((x-mu)*rsqrt(var+eps)*gamma + beta)
// out==nullptr -> write g_x2 (layer 1), else write out (layer 2 / d_out)
// ------------------------------------------------------------------
__global__ void k_bn(const float* __restrict__ gamma,
                     const float* __restrict__ beta,
                     const float* __restrict__ aparam,
                     int off, float* out) {
    int idx = blockIdx.x * 256 + threadIdx.x;  // over NN*32 float4
    if (idx >= NN * 32) return;
    float* O = out ? out : (float*)g_x2;
    int c = (idx & 31) * 4;
    float alpha = aparam[0];
    const float* st = g_stats + off;
    float4 v = ((const float4*)g_agg)[idx];
    float vv[4] = {v.x, v.y, v.z, v.w};
    float oo[4];
#pragma unroll
    for (int j = 0; j < 4; j++) {
        float mu = st[c + j] * (1.0f / NN);
        float var = st[DD + c + j] * (1.0f / NN) - mu * mu;
        float rs = rsqrtf(var + BN_EPS);
        float y = (vv[j] - mu) * rs * __ldg(&gamma[c + j]) + __ldg(&beta[c + j]);
        oo[j] = (y >= 0.f) ? y : alpha * y;
    }
    ((float4*)O)[idx] = make_float4(oo[0], oo[1], oo[2], oo[3]);
}

// ------------------------------------------------------------------
// launch
// ------------------------------------------------------------------
extern "C" void kernel_launch(void* const* d_in, const int* in_sizes, int n_in,
                              void* d_out, int out_size) {
    const float* x      = (const float*)d_in[0];
    const int*   eidx   = (const int*)d_in[1];
    const float* W1     = (const float*)d_in[2];
    const float* b1     = (const float*)d_in[3];
    const float* gamma1 = (const float*)d_in[4];
    const float* beta1  = (const float*)d_in[5];
    const float* a1     = (const float*)d_in[6];
    const float* W2     = (const float*)d_in[7];
    const float* b2     = (const float*)d_in[8];
    const float* gamma2 = (const float*)d_in[9];
    const float* beta2  = (const float*)d_in[10];
    const float* a2     = (const float*)d_in[11];
    float* out = (float*)d_out;

    const int* src = eidx;
    const int* dst = eidx + NE;

    const int smem_gemm = (DD * DD + 64 * DD) * sizeof(float);  // 96 KB
    cudaFuncSetAttribute(k_gemm, cudaFuncAttributeMaxDynamicSharedMemorySize,
                         smem_gemm);

    int nb_nodes = (NN + 255) / 256;
    int nb_edges = (NE + 255) / 256;
    int nb_gemm  = (NN + 63) / 64;
    int nb_elem  = (NN * 32 + 255) / 256;
    int nb_scat  = (NE + 7) / 8;
    int nb_stat  = (NN + 255) / 256;

    // degrees (recomputed every call -> graph-replay safe)
    k_deg_init<<<nb_nodes, 256>>>();
    k_deg_count<<<nb_edges, 256>>>(dst);
    k_dinv<<<nb_nodes, 256>>>();

    // ---- layer 1 ----
    k_gemm<<<nb_gemm, 256, smem_gemm>>>(x, W1, 0);
    k_agg_init<<<nb_elem, 256>>>(b1);
    k_scatter<<<nb_scat, 256>>>(src, dst);
    k_stats<<<nb_stat, 256>>>(0);
    k_bn<<<nb_elem, 256>>>(gamma1, beta1, a1, 0, nullptr);

    // ---- layer 2 ----
    k_gemm<<<nb_gemm, 256, smem_gemm>>>(nullptr, W2, 1);
    k_agg_init<<<nb_elem, 256>>>(b2);
    k_scatter<<<nb_scat, 256>>>(src, dst);
    k_stats<<<nb_stat, 256>>>(2 * DD);
    k_bn<<<nb_elem, 256>>>(gamma2, beta2, a2, 2 * DD, out);
}

// round 2
// speedup vs baseline: 1.1705x; 1.1705x over previous
#include <cuda_runtime.h>

#define NN 50000
#define NE 800000
#define DD 128
#define BN_EPS 1e-5f

// ---- static device scratch ----
__device__ float g_h[NN * DD];     // GEMM output
__device__ float g_agg[NN * DD];   // aggregation output
__device__ int   g_deg[NN];        // in-degree (no self loop)
__device__ float g_dinv[NN];       // (deg+1)^{-1/2}
__device__ int   g_rowstart[NN];   // CSR offsets
__device__ int   g_cursor[NN];     // CSR fill cursors
__device__ int   g_bsum[256];      // scan partials
__device__ int   g_csr_src[NE];    // CSR src ids grouped by dst
__device__ float g_csr_w[NE];      // per-edge norm weight
__device__ float g_stats[4 * DD];  // [sum1|sq1|sum2|sq2]

// ------------------------------------------------------------------
__global__ void k_init() {
    int i = blockIdx.x * 256 + threadIdx.x;
    if (i < NN) g_deg[i] = 0;
    if (i < 4 * DD) g_stats[i] = 0.f;
}

__global__ void k_deg(const int* __restrict__ dst) {
    int e = blockIdx.x * 256 + threadIdx.x;
    if (e < NE) atomicAdd(&g_deg[dst[e]], 1);
}

// block-wide scan (256 threads) of degrees -> local exclusive offsets + block sums
__global__ void k_scan1() {
    __shared__ int wsum[8];
    int tid = threadIdx.x;
    int i = blockIdx.x * 256 + tid;
    int d0 = (i < NN) ? g_deg[i] : 0;
    int v = d0;
    int lane = tid & 31, wid = tid >> 5;
#pragma unroll
    for (int o = 1; o < 32; o <<= 1) {
        int n = __shfl_up_sync(0xffffffffu, v, o);
        if (lane >= o) v += n;
    }
    if (lane == 31) wsum[wid] = v;
    __syncthreads();
    if (wid == 0) {
        int s = (lane < 8) ? wsum[lane] : 0;
#pragma unroll
        for (int o = 1; o < 8; o <<= 1) {
            int n = __shfl_up_sync(0xffffffffu, s, o);
            if (lane >= o) s += n;
        }
        if (lane < 8) wsum[lane] = s;
    }
    __syncthreads();
    int off = (wid > 0) ? wsum[wid - 1] : 0;
    int incl = v + off;
    if (i < NN) {
        g_rowstart[i] = incl - d0;                 // local exclusive
        g_dinv[i] = rsqrtf((float)(d0 + 1));       // +1 self loop
    }
    if (tid == 255) g_bsum[blockIdx.x] = incl;     // block total
}

// scan the (<=256) block sums in-place -> exclusive prefix
__global__ void k_scan2(int nb) {
    __shared__ int wsum[8];
    int tid = threadIdx.x;
    int d0 = (tid < nb) ? g_bsum[tid] : 0;
    int v = d0;
    int lane = tid & 31, wid = tid >> 5;
#pragma unroll
    for (int o = 1; o < 32; o <<= 1) {
        int n = __shfl_up_sync(0xffffffffu, v, o);
        if (lane >= o) v += n;
    }
    if (lane == 31) wsum[wid] = v;
    __syncthreads();
    if (wid == 0) {
        int s = (lane < 8) ? wsum[lane] : 0;
#pragma unroll
        for (int o = 1; o < 8; o <<= 1) {
            int n = __shfl_up_sync(0xffffffffu, s, o);
            if (lane >= o) s += n;
        }
        if (lane < 8) wsum[lane] = s;
    }
    __syncthreads();
    int off = (wid > 0) ? wsum[wid - 1] : 0;
    if (tid < nb) g_bsum[tid] = (v + off) - d0;    // exclusive
}

__global__ void k_scan3() {
    int i = blockIdx.x * 256 + threadIdx.x;
    if (i < NN) {
        int rs = g_rowstart[i] + g_bsum[blockIdx.x];
        g_rowstart[i] = rs;
        g_cursor[i] = rs;
    }
}

__global__ void k_csr(const int* __restrict__ src, const int* __restrict__ dst) {
    int e = blockIdx.x * 256 + threadIdx.x;
    if (e < NE) {
        int s = src[e], d = dst[e];
        int pos = atomicAdd(&g_cursor[d], 1);
        g_csr_src[pos] = s;
        g_csr_w[pos] = g_dinv[s] * g_dinv[d];
    }
}

// ------------------------------------------------------------------
// SGEMM 64x128 tile, 128 threads, 8x8 per thread.
// Optional fused BN+PReLU on the X load (bn_off >= 0).
// smem: W 64KB + Xtile 32KB dynamic.
// ------------------------------------------------------------------
__global__ void __launch_bounds__(128) k_gemm(
        const float* __restrict__ Xin, const float* __restrict__ W,
        const float* __restrict__ gamma, const float* __restrict__ beta,
        const float* __restrict__ aparam, int bn_off, int use_agg) {
    extern __shared__ float smem[];
    float* sW = smem;            // 128*128
    float* sX = smem + DD * DD;  // 64*128
    __shared__ float s_scale[DD];
    __shared__ float s_shift[DD];

    int tid = threadIdx.x;
    int row0 = blockIdx.x * 64;
    const float* X = use_agg ? (const float*)g_agg : Xin;

    float alpha = 0.f;
    if (bn_off >= 0) {
        alpha = aparam[0];
        if (tid < DD) {
            float mu  = g_stats[bn_off + tid] * (1.f / NN);
            float var = g_stats[bn_off + DD + tid] * (1.f / NN) - mu * mu;
            float sc  = gamma[tid] * rsqrtf(var + BN_EPS);
            s_scale[tid] = sc;
            s_shift[tid] = beta[tid] - mu * sc;
        }
    }

    const float4* W4 = (const float4*)W;
    float4* sW4 = (float4*)sW;
#pragma unroll 8
    for (int i = tid; i < DD * DD / 4; i += 128) sW4[i] = W4[i];
    __syncthreads();  // s_scale ready + W loaded

    const float4* X4 = (const float4*)X;
    float4* sX4 = (float4*)sX;
    for (int i = tid; i < 64 * 32; i += 128) {
        int r = i >> 5, c = i & 31;
        int gr = row0 + r;
        float4 v = make_float4(0.f, 0.f, 0.f, 0.f);
        if (gr < NN) v = X4[gr * 32 + c];
        if (bn_off >= 0) {
            int cc = c * 4;
            float y;
            y = v.x * s_scale[cc]     + s_shift[cc];     v.x = (y >= 0.f) ? y : alpha * y;
            y = v.y * s_scale[cc + 1] + s_shift[cc + 1]; v.y = (y >= 0.f) ? y : alpha * y;
            y = v.z * s_scale[cc + 2] + s_shift[cc + 2]; v.z = (y >= 0.f) ? y : alpha * y;
            y = v.w * s_scale[cc + 3] + s_shift[cc + 3]; v.w = (y >= 0.f) ? y : alpha * y;
        }
        sX4[i] = v;
    }
    __syncthreads();

    int tx = tid & 15;   // cols tx*4..+3 and 64+tx*4..+3
    int ty = tid >> 4;   // rows ty*8..+7

    float4 acc0[8], acc1[8];
#pragma unroll
    for (int i = 0; i < 8; i++) {
        acc0[i] = make_float4(0.f, 0.f, 0.f, 0.f);
        acc1[i] = make_float4(0.f, 0.f, 0.f, 0.f);
    }

    const float* xb = sX + ty * 8 * DD;
    for (int k0 = 0; k0 < DD; k0 += 4) {
        float4 xv[8];
#pragma unroll
        for (int i = 0; i < 8; i++)
            xv[i] = *(const float4*)(xb + i * DD + k0);
#pragma unroll
        for (int kk = 0; kk < 4; kk++) {
            const float* wr = sW + (k0 + kk) * DD;
            float4 w0 = *(const float4*)(wr + tx * 4);
            float4 w1 = *(const float4*)(wr + 64 + tx * 4);
#pragma unroll
            for (int i = 0; i < 8; i++) {
                float xs = (kk == 0) ? xv[i].x : (kk == 1) ? xv[i].y
                         : (kk == 2) ? xv[i].z : xv[i].w;
                acc0[i].x += xs * w0.x; acc0[i].y += xs * w0.y;
                acc0[i].z += xs * w0.z; acc0[i].w += xs * w0.w;
                acc1[i].x += xs * w1.x; acc1[i].y += xs * w1.y;
                acc1[i].z += xs * w1.z; acc1[i].w += xs * w1.w;
            }
        }
    }

#pragma unroll
    for (int i = 0; i < 8; i++) {
        int gr = row0 + ty * 8 + i;
        if (gr < NN) {
            *(float4*)(g_h + (size_t)gr * DD + tx * 4)      = acc0[i];
            *(float4*)(g_h + (size_t)gr * DD + 64 + tx * 4) = acc1[i];
        }
    }
}

// ------------------------------------------------------------------
// CSR aggregation: warp per node, lane owns one float4 of the row.
// agg[n] = b + h[n]*dinv[n]^2 + sum_{e in CSR(n)} h[src_e]*w_e
// BN statistics (col sum/sumsq) fused via smem reduction.
// ------------------------------------------------------------------
__global__ void k_agg(const float* __restrict__ bias, int soff) {
    __shared__ float s_sum[DD];
    __shared__ float s_sq[DD];
    int tid = threadIdx.x;
    if (tid < DD) { s_sum[tid] = 0.f; s_sq[tid] = 0.f; }
    __syncthreads();

    int node = blockIdx.x * 8 + (tid >> 5);
    int lane = tid & 31;
    if (node < NN) {
        const float4* h4 = (const float4*)g_h;
        float di = g_dinv[node];
        float w0 = di * di;
        float4 acc = h4[node * 32 + lane];
        float4 bv = ((const float4*)bias)[lane];
        acc.x = acc.x * w0 + bv.x;
        acc.y = acc.y * w0 + bv.y;
        acc.z = acc.z * w0 + bv.z;
        acc.w = acc.w * w0 + bv.w;

        int base = g_rowstart[node];
        int cnt  = g_deg[node];
        int j = 0;
        for (; j + 2 <= cnt; j += 2) {
            int   s0  = __ldg(&g_csr_src[base + j]);
            int   s1  = __ldg(&g_csr_src[base + j + 1]);
            float ww0 = __ldg(&g_csr_w[base + j]);
            float ww1 = __ldg(&g_csr_w[base + j + 1]);
            float4 v0 = h4[s0 * 32 + lane];
            float4 v1 = h4[s1 * 32 + lane];
            acc.x += v0.x * ww0 + v1.x * ww1;
            acc.y += v0.y * ww0 + v1.y * ww1;
            acc.z += v0.z * ww0 + v1.z * ww1;
            acc.w += v0.w * ww0 + v1.w * ww1;
        }
        if (j < cnt) {
            int   s0  = __ldg(&g_csr_src[base + j]);
            float ww0 = __ldg(&g_csr_w[base + j]);
            float4 v0 = h4[s0 * 32 + lane];
            acc.x += v0.x * ww0;
            acc.y += v0.y * ww0;
            acc.z += v0.z * ww0;
            acc.w += v0.w * ww0;
        }
        ((float4*)g_agg)[node * 32 + lane] = acc;

        int c = lane * 4;
        atomicAdd(&s_sum[c],     acc.x);
        atomicAdd(&s_sum[c + 1], acc.y);
        atomicAdd(&s_sum[c + 2], acc.z);
        atomicAdd(&s_sum[c + 3], acc.w);
        atomicAdd(&s_sq[c],      acc.x * acc.x);
        atomicAdd(&s_sq[c + 1],  acc.y * acc.y);
        atomicAdd(&s_sq[c + 2],  acc.z * acc.z);
        atomicAdd(&s_sq[c + 3],  acc.w * acc.w);
    }
    __syncthreads();
    if (tid < DD) {
        atomicAdd(&g_stats[soff + tid],      s_sum[tid]);
        atomicAdd(&g_stats[soff + DD + tid], s_sq[tid]);
    }
}

// ------------------------------------------------------------------
// final BN + PReLU -> d_out
// ------------------------------------------------------------------
__global__ void k_bn_out(const float* __restrict__ gamma,
                         const float* __restrict__ beta,
                         const float* __restrict__ aparam,
                         int soff, float* __restrict__ out) {
    int idx = blockIdx.x * 256 + threadIdx.x;
    if (idx >= NN * 32) return;
    int c = (idx & 31) * 4;
    float alpha = aparam[0];
    float4 v = ((const float4*)g_agg)[idx];
    float vv[4] = {v.x, v.y, v.z, v.w};
    float oo[4];
#pragma unroll
    for (int j = 0; j < 4; j++) {
        float mu  = g_stats[soff + c + j] * (1.f / NN);
        float var = g_stats[soff + DD + c + j] * (1.f / NN) - mu * mu;
        float rs  = rsqrtf(var + BN_EPS);
        float y = (vv[j] - mu) * rs * __ldg(&gamma[c + j]) + __ldg(&beta[c + j]);
        oo[j] = (y >= 0.f) ? y : alpha * y;
    }
    ((float4*)out)[idx] = make_float4(oo[0], oo[1], oo[2], oo[3]);
}

// ------------------------------------------------------------------
extern "C" void kernel_launch(void* const* d_in, const int* in_sizes, int n_in,
                              void* d_out, int out_size) {
    const float* x      = (const float*)d_in[0];
    const int*   eidx   = (const int*)d_in[1];
    const float* W1     = (const float*)d_in[2];
    const float* b1     = (const float*)d_in[3];
    const float* gamma1 = (const float*)d_in[4];
    const float* beta1  = (const float*)d_in[5];
    const float* a1     = (const float*)d_in[6];
    const float* W2     = (const float*)d_in[7];
    const float* b2     = (const float*)d_in[8];
    const float* gamma2 = (const float*)d_in[9];
    const float* beta2  = (const float*)d_in[10];
    const float* a2     = (const float*)d_in[11];
    float* out = (float*)d_out;

    const int* src = eidx;
    const int* dst = eidx + NE;

    const int smem_gemm = (DD * DD + 64 * DD) * sizeof(float);  // 96 KB
    cudaFuncSetAttribute(k_gemm, cudaFuncAttributeMaxDynamicSharedMemorySize,
                         smem_gemm);

    int nb_scan = (NN + 255) / 256;  // 196
    int nb_edge = (NE + 255) / 256;  // 3125

    // ---- graph preprocessing (once per call, shared by both layers) ----
    k_init<<<nb_scan, 256>>>();
    k_deg<<<nb_edge, 256>>>(dst);
    k_scan1<<<nb_scan, 256>>>();
    k_scan2<<<1, 256>>>(nb_scan);
    k_scan3<<<nb_scan, 256>>>();
    k_csr<<<nb_edge, 256>>>(src, dst);

    int nb_gemm = (NN + 63) / 64;
    int nb_agg  = (NN + 7) / 8;
    int nb_elem = (NN * 32 + 255) / 256;

    // ---- layer 1 ----
    k_gemm<<<nb_gemm, 128, smem_gemm>>>(x, W1, nullptr, nullptr, nullptr, -1, 0);
    k_agg<<<nb_agg, 256>>>(b1, 0);

    // ---- layer 2 (BN1+PReLU fused into the GEMM X load) ----
    k_gemm<<<nb_gemm, 128, smem_gemm>>>(nullptr, W2, gamma1, beta1, a1, 0, 1);
    k_agg<<<nb_agg, 256>>>(b2, 2 * DD);

    // ---- final BN2 + PReLU -> output ----
    k_bn_out<<<nb_elem, 256>>>(gamma2, beta2, a2, 2 * DD, out);
}

// round 3
// speedup vs baseline: 1.2465x; 1.0649x over previous
#include <cuda_runtime.h>

#define NN 50000
#define NE 800000
#define DD 128
#define BN_EPS 1e-5f

// ---- static device scratch ----
__device__ float g_h[NN * DD];     // GEMM output
__device__ float g_agg[NN * DD];   // aggregation output
__device__ int   g_deg[NN];        // in-degree (no self loop)
__device__ float g_dinv[NN];       // (deg+1)^{-1/2}
__device__ int   g_rowstart[NN];   // CSR offsets
__device__ int   g_cursor[NN];     // CSR fill cursors
__device__ int   g_bsum[256];      // scan partials
__device__ int2  g_csre[NE];       // CSR packed (src, weight-bits) grouped by dst
__device__ float g_stats[4 * DD];  // [sum1|sq1|sum2|sq2]

// ------------------------------------------------------------------
// degree count: 4 edges per thread via int4
// ------------------------------------------------------------------
__global__ void k_deg(const int* __restrict__ dst) {
    int t = blockIdx.x * 256 + threadIdx.x;
    if (t * 4 < NE) {
        int4 d = ((const int4*)dst)[t];
        atomicAdd(&g_deg[d.x], 1);
        atomicAdd(&g_deg[d.y], 1);
        atomicAdd(&g_deg[d.z], 1);
        atomicAdd(&g_deg[d.w], 1);
    }
}

// block-wide scan (256 threads) of degrees -> local exclusive offsets + block sums
__global__ void k_scan1() {
    __shared__ int wsum[8];
    int tid = threadIdx.x;
    int i = blockIdx.x * 256 + tid;
    int d0 = (i < NN) ? g_deg[i] : 0;
    int v = d0;
    int lane = tid & 31, wid = tid >> 5;
#pragma unroll
    for (int o = 1; o < 32; o <<= 1) {
        int n = __shfl_up_sync(0xffffffffu, v, o);
        if (lane >= o) v += n;
    }
    if (lane == 31) wsum[wid] = v;
    __syncthreads();
    if (wid == 0) {
        int s = (lane < 8) ? wsum[lane] : 0;
#pragma unroll
        for (int o = 1; o < 8; o <<= 1) {
            int n = __shfl_up_sync(0xffffffffu, s, o);
            if (lane >= o) s += n;
        }
        if (lane < 8) wsum[lane] = s;
    }
    __syncthreads();
    int off = (wid > 0) ? wsum[wid - 1] : 0;
    int incl = v + off;
    if (i < NN) {
        g_rowstart[i] = incl - d0;                 // local exclusive
        g_dinv[i] = rsqrtf((float)(d0 + 1));       // +1 self loop
    }
    if (tid == 255) g_bsum[blockIdx.x] = incl;     // block total
}

__global__ void k_scan2(int nb) {
    __shared__ int wsum[8];
    int tid = threadIdx.x;
    int d0 = (tid < nb) ? g_bsum[tid] : 0;
    int v = d0;
    int lane = tid & 31, wid = tid >> 5;
#pragma unroll
    for (int o = 1; o < 32; o <<= 1) {
        int n = __shfl_up_sync(0xffffffffu, v, o);
        if (lane >= o) v += n;
    }
    if (lane == 31) wsum[wid] = v;
    __syncthreads();
    if (wid == 0) {
        int s = (lane < 8) ? wsum[lane] : 0;
#pragma unroll
        for (int o = 1; o < 8; o <<= 1) {
            int n = __shfl_up_sync(0xffffffffu, s, o);
            if (lane >= o) s += n;
        }
        if (lane < 8) wsum[lane] = s;
    }
    __syncthreads();
    int off = (wid > 0) ? wsum[wid - 1] : 0;
    if (tid < nb) g_bsum[tid] = (v + off) - d0;    // exclusive
}

__global__ void k_scan3() {
    int i = blockIdx.x * 256 + threadIdx.x;
    if (i < NN) {
        int rs = g_rowstart[i] + g_bsum[blockIdx.x];
        g_rowstart[i] = rs;
        g_cursor[i] = rs;
    }
}

__global__ void k_csr(const int* __restrict__ src, const int* __restrict__ dst) {
    int e = blockIdx.x * 256 + threadIdx.x;
    if (e < NE) {
        int s = src[e], d = dst[e];
        int pos = atomicAdd(&g_cursor[d], 1);
        float w = g_dinv[s] * g_dinv[d];
        g_csre[pos] = make_int2(s, __float_as_int(w));
    }
}

// ------------------------------------------------------------------
// SGEMM 64x128 tile, 128 threads, 8x8 per thread.
// Optional fused BN+PReLU on the X load (bn_off >= 0).
// smem: W 64KB + Xtile 32KB dynamic.
// ------------------------------------------------------------------
__global__ void __launch_bounds__(128) k_gemm(
        const float* __restrict__ Xin, const float* __restrict__ W,
        const float* __restrict__ gamma, const float* __restrict__ beta,
        const float* __restrict__ aparam, int bn_off, int use_agg) {
    extern __shared__ float smem[];
    float* sW = smem;            // 128*128
    float* sX = smem + DD * DD;  // 64*128
    __shared__ float s_scale[DD];
    __shared__ float s_shift[DD];

    int tid = threadIdx.x;
    int row0 = blockIdx.x * 64;
    const float* X = use_agg ? (const float*)g_agg : Xin;

    float alpha = 0.f;
    if (bn_off >= 0) {
        alpha = aparam[0];
        if (tid < DD) {
            float mu  = g_stats[bn_off + tid] * (1.f / NN);
            float var = g_stats[bn_off + DD + tid] * (1.f / NN) - mu * mu;
            float sc  = gamma[tid] * rsqrtf(var + BN_EPS);
            s_scale[tid] = sc;
            s_shift[tid] = beta[tid] - mu * sc;
        }
    }

    const float4* W4 = (const float4*)W;
    float4* sW4 = (float4*)sW;
#pragma unroll 8
    for (int i = tid; i < DD * DD / 4; i += 128) sW4[i] = W4[i];
    __syncthreads();  // s_scale ready + W loaded

    const float4* X4 = (const float4*)X;
    float4* sX4 = (float4*)sX;
    for (int i = tid; i < 64 * 32; i += 128) {
        int r = i >> 5, c = i & 31;
        int gr = row0 + r;
        float4 v = make_float4(0.f, 0.f, 0.f, 0.f);
        if (gr < NN) v = X4[gr * 32 + c];
        if (bn_off >= 0) {
            int cc = c * 4;
            float y;
            y = v.x * s_scale[cc]     + s_shift[cc];     v.x = (y >= 0.f) ? y : alpha * y;
            y = v.y * s_scale[cc + 1] + s_shift[cc + 1]; v.y = (y >= 0.f) ? y : alpha * y;
            y = v.z * s_scale[cc + 2] + s_shift[cc + 2]; v.z = (y >= 0.f) ? y : alpha * y;
            y = v.w * s_scale[cc + 3] + s_shift[cc + 3]; v.w = (y >= 0.f) ? y : alpha * y;
        }
        sX4[i] = v;
    }
    __syncthreads();

    int tx = tid & 15;   // cols tx*4..+3 and 64+tx*4..+3
    int ty = tid >> 4;   // rows ty*8..+7

    float4 acc0[8], acc1[8];
#pragma unroll
    for (int i = 0; i < 8; i++) {
        acc0[i] = make_float4(0.f, 0.f, 0.f, 0.f);
        acc1[i] = make_float4(0.f, 0.f, 0.f, 0.f);
    }

    const float* xb = sX + ty * 8 * DD;
    for (int k0 = 0; k0 < DD; k0 += 4) {
        float4 xv[8];
#pragma unroll
        for (int i = 0; i < 8; i++)
            xv[i] = *(const float4*)(xb + i * DD + k0);
#pragma unroll
        for (int kk = 0; kk < 4; kk++) {
            const float* wr = sW + (k0 + kk) * DD;
            float4 w0 = *(const float4*)(wr + tx * 4);
            float4 w1 = *(const float4*)(wr + 64 + tx * 4);
#pragma unroll
            for (int i = 0; i < 8; i++) {
                float xs = (kk == 0) ? xv[i].x : (kk == 1) ? xv[i].y
                         : (kk == 2) ? xv[i].z : xv[i].w;
                acc0[i].x += xs * w0.x; acc0[i].y += xs * w0.y;
                acc0[i].z += xs * w0.z; acc0[i].w += xs * w0.w;
                acc1[i].x += xs * w1.x; acc1[i].y += xs * w1.y;
                acc1[i].z += xs * w1.z; acc1[i].w += xs * w1.w;
            }
        }
    }

#pragma unroll
    for (int i = 0; i < 8; i++) {
        int gr = row0 + ty * 8 + i;
        if (gr < NN) {
            *(float4*)(g_h + (size_t)gr * DD + tx * 4)      = acc0[i];
            *(float4*)(g_h + (size_t)gr * DD + 64 + tx * 4) = acc1[i];
        }
    }
}

// ------------------------------------------------------------------
// CSR aggregation: warp per node, lane owns one float4 of the row.
// 4-wide unrolled gathers for MLP; packed (src,w) int2 edge stream.
// BN statistics fused via smem reduction.
// ------------------------------------------------------------------
__global__ void k_agg(const float* __restrict__ bias, int soff) {
    __shared__ float s_sum[DD];
    __shared__ float s_sq[DD];
    int tid = threadIdx.x;
    if (tid < DD) { s_sum[tid] = 0.f; s_sq[tid] = 0.f; }
    __syncthreads();

    int node = blockIdx.x * 8 + (tid >> 5);
    int lane = tid & 31;
    if (node < NN) {
        const float4* h4 = (const float4*)g_h;
        float di = g_dinv[node];
        float w0 = di * di;
        float4 acc = h4[node * 32 + lane];
        float4 bv = ((const float4*)bias)[lane];
        acc.x = acc.x * w0 + bv.x;
        acc.y = acc.y * w0 + bv.y;
        acc.z = acc.z * w0 + bv.z;
        acc.w = acc.w * w0 + bv.w;

        int base = g_rowstart[node];
        int cnt  = g_deg[node];
        const int2* ep = g_csre + base;
        int j = 0;
        for (; j + 4 <= cnt; j += 4) {
            int2 e0 = __ldg(ep + j);
            int2 e1 = __ldg(ep + j + 1);
            int2 e2 = __ldg(ep + j + 2);
            int2 e3 = __ldg(ep + j + 3);
            float4 v0 = h4[e0.x * 32 + lane];
            float4 v1 = h4[e1.x * 32 + lane];
            float4 v2 = h4[e2.x * 32 + lane];
            float4 v3 = h4[e3.x * 32 + lane];
            float w1f = __int_as_float(e0.y), w2f = __int_as_float(e1.y);
            float w3f = __int_as_float(e2.y), w4f = __int_as_float(e3.y);
            acc.x += v0.x * w1f + v1.x * w2f + v2.x * w3f + v3.x * w4f;
            acc.y += v0.y * w1f + v1.y * w2f + v2.y * w3f + v3.y * w4f;
            acc.z += v0.z * w1f + v1.z * w2f + v2.z * w3f + v3.z * w4f;
            acc.w += v0.w * w1f + v1.w * w2f + v2.w * w3f + v3.w * w4f;
        }
        for (; j < cnt; j++) {
            int2 e0 = __ldg(ep + j);
            float4 v0 = h4[e0.x * 32 + lane];
            float wf = __int_as_float(e0.y);
            acc.x += v0.x * wf;
            acc.y += v0.y * wf;
            acc.z += v0.z * wf;
            acc.w += v0.w * wf;
        }
        ((float4*)g_agg)[node * 32 + lane] = acc;

        int c = lane * 4;
        atomicAdd(&s_sum[c],     acc.x);
        atomicAdd(&s_sum[c + 1], acc.y);
        atomicAdd(&s_sum[c + 2], acc.z);
        atomicAdd(&s_sum[c + 3], acc.w);
        atomicAdd(&s_sq[c],      acc.x * acc.x);
        atomicAdd(&s_sq[c + 1],  acc.y * acc.y);
        atomicAdd(&s_sq[c + 2],  acc.z * acc.z);
        atomicAdd(&s_sq[c + 3],  acc.w * acc.w);
    }
    __syncthreads();
    if (tid < DD) {
        atomicAdd(&g_stats[soff + tid],      s_sum[tid]);
        atomicAdd(&g_stats[soff + DD + tid], s_sq[tid]);
    }
}

// ------------------------------------------------------------------
// final BN + PReLU -> d_out
// ------------------------------------------------------------------
__global__ void k_bn_out(const float* __restrict__ gamma,
                         const float* __restrict__ beta,
                         const float* __restrict__ aparam,
                         int soff, float* __restrict__ out) {
    int idx = blockIdx.x * 256 + threadIdx.x;
    if (idx >= NN * 32) return;
    int c = (idx & 31) * 4;
    float alpha = aparam[0];
    float4 v = ((const float4*)g_agg)[idx];
    float vv[4] = {v.x, v.y, v.z, v.w};
    float oo[4];
#pragma unroll
    for (int j = 0; j < 4; j++) {
        float mu  = g_stats[soff + c + j] * (1.f / NN);
        float var = g_stats[soff + DD + c + j] * (1.f / NN) - mu * mu;
        float rs  = rsqrtf(var + BN_EPS);
        float y = (vv[j] - mu) * rs * __ldg(&gamma[c + j]) + __ldg(&beta[c + j]);
        oo[j] = (y >= 0.f) ? y : alpha * y;
    }
    ((float4*)out)[idx] = make_float4(oo[0], oo[1], oo[2], oo[3]);
}

// ------------------------------------------------------------------
extern "C" void kernel_launch(void* const* d_in, const int* in_sizes, int n_in,
                              void* d_out, int out_size) {
    const float* x      = (const float*)d_in[0];
    const int*   eidx   = (const int*)d_in[1];
    const float* W1     = (const float*)d_in[2];
    const float* b1     = (const float*)d_in[3];
    const float* gamma1 = (const float*)d_in[4];
    const float* beta1  = (const float*)d_in[5];
    const float* a1     = (const float*)d_in[6];
    const float* W2     = (const float*)d_in[7];
    const float* b2     = (const float*)d_in[8];
    const float* gamma2 = (const float*)d_in[9];
    const float* beta2  = (const float*)d_in[10];
    const float* a2     = (const float*)d_in[11];
    float* out = (float*)d_out;

    const int* src = eidx;
    const int* dst = eidx + NE;

    // one-time setup (first call = correctness run, before graph capture)
    static bool s_init = false;
    static cudaStream_t s_side = nullptr;
    static cudaEvent_t ev_fork = nullptr, ev_join = nullptr;
    static void* p_deg = nullptr;
    static void* p_stats = nullptr;
    if (!s_init) {
        s_init = true;
        cudaGetSymbolAddress(&p_deg, g_deg);
        cudaGetSymbolAddress(&p_stats, g_stats);
        if (cudaStreamCreateWithFlags(&s_side, cudaStreamNonBlocking) == cudaSuccess) {
            if (cudaEventCreateWithFlags(&ev_fork, cudaEventDisableTiming) != cudaSuccess ||
                cudaEventCreateWithFlags(&ev_join, cudaEventDisableTiming) != cudaSuccess) {
                s_side = nullptr;
            }
        } else {
            s_side = nullptr;
        }
        const int smem_gemm = (DD * DD + 64 * DD) * sizeof(float);
        cudaFuncSetAttribute(k_gemm, cudaFuncAttributeMaxDynamicSharedMemorySize,
                             smem_gemm);
    }

    const int smem_gemm = (DD * DD + 64 * DD) * sizeof(float);  // 96 KB
    int nb_scan = (NN + 255) / 256;            // 196
    int nb_edge = (NE + 255) / 256;            // 3125
    int nb_deg  = (NE / 4 + 255) / 256;        // 782
    int nb_gemm = (NN + 63) / 64;
    int nb_agg  = (NN + 7) / 8;
    int nb_elem = (NN * 32 + 255) / 256;

    cudaStream_t sp = s_side ? s_side : (cudaStream_t)0;  // preprocessing stream

    // fork: preprocessing runs concurrent with GEMM-1
    if (s_side) {
        cudaEventRecord(ev_fork, 0);
        cudaStreamWaitEvent(s_side, ev_fork, 0);
    }

    // ---- preprocessing chain (side stream) ----
    cudaMemsetAsync(p_deg, 0, NN * sizeof(int), sp);
    k_deg<<<nb_deg, 256, 0, sp>>>(dst);
    k_scan1<<<nb_scan, 256, 0, sp>>>();
    k_scan2<<<1, 256, 0, sp>>>(nb_scan);
    k_scan3<<<nb_scan, 256, 0, sp>>>();
    k_csr<<<nb_edge, 256, 0, sp>>>(src, dst);

    // ---- main stream: stats clear + GEMM-1 ----
    cudaMemsetAsync(p_stats, 0, 4 * DD * sizeof(float), 0);
    k_gemm<<<nb_gemm, 128, smem_gemm>>>(x, W1, nullptr, nullptr, nullptr, -1, 0);

    // join
    if (s_side) {
        cudaEventRecord(ev_join, s_side);
        cudaStreamWaitEvent(0, ev_join, 0);
    }

    // ---- layer 1 aggregation ----
    k_agg<<<nb_agg, 256>>>(b1, 0);

    // ---- layer 2 (BN1+PReLU fused into GEMM X load) ----
    k_gemm<<<nb_gemm, 128, smem_gemm>>>(nullptr, W2, gamma1, beta1, a1, 0, 1);
    k_agg<<<nb_agg, 256>>>(b2, 2 * DD);

    // ---- final BN2 + PReLU -> output ----
    k_bn_out<<<nb_elem, 256>>>(gamma2, beta2, a2, 2 * DD, out);
}

// round 5
// speedup vs baseline: 1.4711x; 1.1802x over previous
#include <cuda_runtime.h>
#include <cuda_bf16.h>
#include <cstdint>

#define NN 50000
#define NE 800000
#define DD 128
#define BN_EPS 1e-5f
#define WSTRIDE 136                      // padded row stride (bf16 elems)
#define WTILE_BYTES (DD * WSTRIDE * 2)   // 34816 bytes per 128x128 bf16 tile

// ---- static device scratch ----
__device__ float g_h[NN * DD];
__device__ float g_agg[NN * DD];
__device__ int   g_deg[NN];
__device__ float g_dinv[NN];
__device__ int   g_rowstart[NN];
__device__ int   g_cursor[NN];
__device__ int   g_bsum[256];
__device__ int2  g_csre[NE];
__device__ float g_stats[4 * DD];
// prepacked Wt[n][k] hi/lo, padded stride (raw-copyable into smem)
__device__ __align__(16) unsigned short g_w1h[DD * WSTRIDE];
__device__ __align__(16) unsigned short g_w1l[DD * WSTRIDE];
__device__ __align__(16) unsigned short g_w2h[DD * WSTRIDE];
__device__ __align__(16) unsigned short g_w2l[DD * WSTRIDE];

// ================= helpers =================
__device__ __forceinline__ uint32_t smem_u32(const void* p) {
    uint32_t a;
    asm("{ .reg .u64 t; cvta.to.shared.u64 t, %1; cvt.u32.u64 %0, t; }"
        : "=r"(a) : "l"(p));
    return a;
}
__device__ __forceinline__ void ldsm4(uint32_t& r0, uint32_t& r1,
                                      uint32_t& r2, uint32_t& r3, uint32_t addr) {
    asm volatile("ldmatrix.sync.aligned.m8n8.x4.shared.b16 {%0,%1,%2,%3}, [%4];"
                 : "=r"(r0), "=r"(r1), "=r"(r2), "=r"(r3) : "r"(addr));
}
__device__ __forceinline__ void ldsm2(uint32_t& r0, uint32_t& r1, uint32_t addr) {
    asm volatile("ldmatrix.sync.aligned.m8n8.x2.shared.b16 {%0,%1}, [%2];"
                 : "=r"(r0), "=r"(r1) : "r"(addr));
}
__device__ __forceinline__ void mma16816(float* c, uint32_t a0, uint32_t a1,
                                         uint32_t a2, uint32_t a3,
                                         uint32_t b0, uint32_t b1) {
    asm volatile("mma.sync.aligned.m16n8k16.row.col.f32.bf16.bf16.f32 "
                 "{%0,%1,%2,%3}, {%4,%5,%6,%7}, {%8,%9}, {%0,%1,%2,%3};"
                 : "+f"(c[0]), "+f"(c[1]), "+f"(c[2]), "+f"(c[3])
                 : "r"(a0), "r"(a1), "r"(a2), "r"(a3), "r"(b0), "r"(b1));
}
__device__ __forceinline__ unsigned short bf_hi(float x) {
    __nv_bfloat16 b = __float2bfloat16(x);
    return *reinterpret_cast<unsigned short*>(&b);
}
__device__ __forceinline__ float bf_val(unsigned short u) {
    __nv_bfloat16 b = *reinterpret_cast<__nv_bfloat16*>(&u);
    return __bfloat162float(b);
}

// ================= graph preprocessing =================
__global__ void k_deg(const int* __restrict__ dst) {
    int t = blockIdx.x * 256 + threadIdx.x;
    if (t * 4 < NE) {
        int4 d = ((const int4*)dst)[t];
        atomicAdd(&g_deg[d.x], 1);
        atomicAdd(&g_deg[d.y], 1);
        atomicAdd(&g_deg[d.z], 1);
        atomicAdd(&g_deg[d.w], 1);
    }
}

__global__ void k_scan1() {
    __shared__ int wsum[8];
    int tid = threadIdx.x;
    int i = blockIdx.x * 256 + tid;
    int d0 = (i < NN) ? g_deg[i] : 0;
    int v = d0;
    int lane = tid & 31, wid = tid >> 5;
#pragma unroll
    for (int o = 1; o < 32; o <<= 1) {
        int n = __shfl_up_sync(0xffffffffu, v, o);
        if (lane >= o) v += n;
    }
    if (lane == 31) wsum[wid] = v;
    __syncthreads();
    if (wid == 0) {
        int s = (lane < 8) ? wsum[lane] : 0;
#pragma unroll
        for (int o = 1; o < 8; o <<= 1) {
            int n = __shfl_up_sync(0xffffffffu, s, o);
            if (lane >= o) s += n;
        }
        if (lane < 8) wsum[lane] = s;
    }
    __syncthreads();
    int off = (wid > 0) ? wsum[wid - 1] : 0;
    int incl = v + off;
    if (i < NN) {
        g_rowstart[i] = incl - d0;
        g_dinv[i] = rsqrtf((float)(d0 + 1));
    }
    if (tid == 255) g_bsum[blockIdx.x] = incl;
}

__global__ void k_scan2(int nb) {
    __shared__ int wsum[8];
    int tid = threadIdx.x;
    int d0 = (tid < nb) ? g_bsum[tid] : 0;
    int v = d0;
    int lane = tid & 31, wid = tid >> 5;
#pragma unroll
    for (int o = 1; o < 32; o <<= 1) {
        int n = __shfl_up_sync(0xffffffffu, v, o);
        if (lane >= o) v += n;
    }
    if (lane == 31) wsum[wid] = v;
    __syncthreads();
    if (wid == 0) {
        int s = (lane < 8) ? wsum[lane] : 0;
#pragma unroll
        for (int o = 1; o < 8; o <<= 1) {
            int n = __shfl_up_sync(0xffffffffu, s, o);
            if (lane >= o) s += n;
        }
        if (lane < 8) wsum[lane] = s;
    }
    __syncthreads();
    int off = (wid > 0) ? wsum[wid - 1] : 0;
    if (tid < nb) g_bsum[tid] = (v + off) - d0;
}

__global__ void k_scan3() {
    int i = blockIdx.x * 256 + threadIdx.x;
    if (i < NN) {
        int rs = g_rowstart[i] + g_bsum[blockIdx.x];
        g_rowstart[i] = rs;
        g_cursor[i] = rs;
    }
}

__global__ void k_csr(const int* __restrict__ src, const int* __restrict__ dst) {
    int e = blockIdx.x * 256 + threadIdx.x;
    if (e < NE) {
        int s = src[e], d = dst[e];
        int pos = atomicAdd(&g_cursor[d], 1);
        float w = g_dinv[s] * g_dinv[d];
        g_csre[pos] = make_int2(s, __float_as_int(w));
    }
}

// ================= W prepack: Wt[n][k] hi/lo, padded stride =================
__global__ void k_wprep(const float* __restrict__ W1, const float* __restrict__ W2) {
    int i = blockIdx.x * 256 + threadIdx.x;
    if (i >= 2 * DD * DD) return;
    int layer = i >> 14;
    int idx = i & (DD * DD - 1);
    int k = idx >> 7, n = idx & 127;
    float w = (layer ? W2 : W1)[idx];
    unsigned short h = bf_hi(w);
    unsigned short l = bf_hi(w - bf_val(h));
    int o = n * WSTRIDE + k;
    if (layer) { g_w2h[o] = h; g_w2l[o] = l; }
    else       { g_w1h[o] = h; g_w1l[o] = l; }
}

// ================= bf16 mma GEMM: 128-row tile, 3-term split =================
// dyn smem: [Xh][Xl][Wh][Wl], each 128 x 136 bf16 = 34816 B -> 139264 total
#define XH_OFF 0
#define XL_OFF WTILE_BYTES
#define WH_OFF (2 * WTILE_BYTES)
#define WL_OFF (3 * WTILE_BYTES)
#define SMEM_MMA (4 * WTILE_BYTES)

__global__ void __launch_bounds__(256) k_gemm_mma(
        const float* __restrict__ Xin,
        const unsigned short* __restrict__ Wh, const unsigned short* __restrict__ Wl,
        const float* __restrict__ gamma, const float* __restrict__ beta,
        const float* __restrict__ aparam, int bn_off, int use_agg) {
    extern __shared__ char sm[];
    __shared__ float s_scale[DD];
    __shared__ float s_shift[DD];

    int tid = threadIdx.x;
    int wid = tid >> 5, lane = tid & 31;
    int row0 = blockIdx.x * 128;
    const float* X = use_agg ? (const float*)g_agg : Xin;

    float alpha = 0.f;
    if (bn_off >= 0) {
        alpha = aparam[0];
        if (tid < DD) {
            float mu  = g_stats[bn_off + tid] * (1.f / NN);
            float var = g_stats[bn_off + DD + tid] * (1.f / NN) - mu * mu;
            float sc  = gamma[tid] * rsqrtf(var + BN_EPS);
            s_scale[tid] = sc;
            s_shift[tid] = beta[tid] - mu * sc;
        }
    }

    // copy prepacked W hi/lo (raw, padded layout preserved)
    {
        const float4* sh = (const float4*)Wh;
        const float4* sl = (const float4*)Wl;
        float4* dh = (float4*)(sm + WH_OFF);
        float4* dl = (float4*)(sm + WL_OFF);
#pragma unroll 4
        for (int i = tid; i < WTILE_BYTES / 16; i += 256) { dh[i] = sh[i]; dl[i] = sl[i]; }
    }
    __syncthreads();  // s_scale ready for X split

    // load X tile (optional BN+PReLU), split hi/lo into padded smem
    {
        const float4* X4 = (const float4*)X;
#pragma unroll 4
        for (int i = tid; i < 128 * 32; i += 256) {
            int r = i >> 5, c = i & 31;
            int gr = row0 + r;
            float4 v = make_float4(0.f, 0.f, 0.f, 0.f);
            if (gr < NN) v = X4[gr * 32 + c];
            if (bn_off >= 0) {
                int cc = c * 4;
                float y;
                y = v.x * s_scale[cc]     + s_shift[cc];     v.x = (y >= 0.f) ? y : alpha * y;
                y = v.y * s_scale[cc + 1] + s_shift[cc + 1]; v.y = (y >= 0.f) ? y : alpha * y;
                y = v.z * s_scale[cc + 2] + s_shift[cc + 2]; v.z = (y >= 0.f) ? y : alpha * y;
                y = v.w * s_scale[cc + 3] + s_shift[cc + 3]; v.w = (y >= 0.f) ? y : alpha * y;
            }
            unsigned short h0 = bf_hi(v.x), h1 = bf_hi(v.y), h2 = bf_hi(v.z), h3 = bf_hi(v.w);
            unsigned short l0 = bf_hi(v.x - bf_val(h0));
            unsigned short l1 = bf_hi(v.y - bf_val(h1));
            unsigned short l2 = bf_hi(v.z - bf_val(h2));
            unsigned short l3 = bf_hi(v.w - bf_val(h3));
            int o = r * (WSTRIDE * 2) + c * 8;
            *(uint2*)(sm + XH_OFF + o) = make_uint2((uint32_t)h0 | ((uint32_t)h1 << 16),
                                                    (uint32_t)h2 | ((uint32_t)h3 << 16));
            *(uint2*)(sm + XL_OFF + o) = make_uint2((uint32_t)l0 | ((uint32_t)l1 << 16),
                                                    (uint32_t)l2 | ((uint32_t)l3 << 16));
        }
    }
    __syncthreads();

    // fragment addresses
    int wrow0 = wid * 16;
    uint32_t base = smem_u32(sm);
    uint32_t a_h = base + XH_OFF + (wrow0 + (lane & 15)) * (WSTRIDE * 2) + (lane >> 4) * 16;
    uint32_t a_l = a_h + (XL_OFF - XH_OFF);
    uint32_t b_h = base + WH_OFF + (lane & 7) * (WSTRIDE * 2) + ((lane >> 3) & 1) * 16;
    uint32_t b_l = b_h + (WL_OFF - WH_OFF);

    float acc[16][4];
#pragma unroll
    for (int nt = 0; nt < 16; nt++)
#pragma unroll
        for (int j = 0; j < 4; j++) acc[nt][j] = 0.f;

#pragma unroll 1
    for (int p = 0; p < 3; p++) {
        uint32_t aa = (p == 2) ? a_l : a_h;
        uint32_t bb = (p == 1) ? b_l : b_h;
#pragma unroll 1
        for (int k = 0; k < 8; k++) {
            uint32_t a0, a1, a2, a3;
            ldsm4(a0, a1, a2, a3, aa + k * 32);
#pragma unroll
            for (int nt = 0; nt < 16; nt++) {
                uint32_t b0, b1;
                ldsm2(b0, b1, bb + k * 32 + nt * 8 * (WSTRIDE * 2));
                mma16816(acc[nt], a0, a1, a2, a3, b0, b1);
            }
        }
    }

    // epilogue: thread holds rows (g, g+8), cols (2t, 2t+1) per n-tile
    int g = lane >> 2, t = lane & 3;
    int r1 = row0 + wrow0 + g;
    int r2 = r1 + 8;
#pragma unroll
    for (int nt = 0; nt < 16; nt++) {
        int col = nt * 8 + t * 2;
        if (r1 < NN)
            *(float2*)(g_h + (size_t)r1 * DD + col) = make_float2(acc[nt][0], acc[nt][1]);
        if (r2 < NN)
            *(float2*)(g_h + (size_t)r2 * DD + col) = make_float2(acc[nt][2], acc[nt][3]);
    }
}

// ================= CSR aggregation (+ fused BN stats) =================
__global__ void k_agg(const float* __restrict__ bias, int soff) {
    __shared__ float s_sum[DD];
    __shared__ float s_sq[DD];
    int tid = threadIdx.x;
    if (tid < DD) { s_sum[tid] = 0.f; s_sq[tid] = 0.f; }
    __syncthreads();

    int node = blockIdx.x * 8 + (tid >> 5);
    int lane = tid & 31;
    if (node < NN) {
        const float4* h4 = (const float4*)g_h;
        float di = g_dinv[node];
        float w0 = di * di;
        float4 acc = h4[node * 32 + lane];
        float4 bv = ((const float4*)bias)[lane];
        acc.x = acc.x * w0 + bv.x;
        acc.y = acc.y * w0 + bv.y;
        acc.z = acc.z * w0 + bv.z;
        acc.w = acc.w * w0 + bv.w;

        int base = g_rowstart[node];
        int cnt  = g_deg[node];
        const int2* ep = g_csre + base;
        int j = 0;
        for (; j + 4 <= cnt; j += 4) {
            int2 e0 = __ldg(ep + j);
            int2 e1 = __ldg(ep + j + 1);
            int2 e2 = __ldg(ep + j + 2);
            int2 e3 = __ldg(ep + j + 3);
            float4 v0 = h4[e0.x * 32 + lane];
            float4 v1 = h4[e1.x * 32 + lane];
            float4 v2 = h4[e2.x * 32 + lane];
            float4 v3 = h4[e3.x * 32 + lane];
            float w1f = __int_as_float(e0.y), w2f = __int_as_float(e1.y);
            float w3f = __int_as_float(e2.y), w4f = __int_as_float(e3.y);
            acc.x += v0.x * w1f + v1.x * w2f + v2.x * w3f + v3.x * w4f;
            acc.y += v0.y * w1f + v1.y * w2f + v2.y * w3f + v3.y * w4f;
            acc.z += v0.z * w1f + v1.z * w2f + v2.z * w3f + v3.z * w4f;
            acc.w += v0.w * w1f + v1.w * w2f + v2.w * w3f + v3.w * w4f;
        }
        for (; j < cnt; j++) {
            int2 e0 = __ldg(ep + j);
            float4 v0 = h4[e0.x * 32 + lane];
            float wf = __int_as_float(e0.y);
            acc.x += v0.x * wf;
            acc.y += v0.y * wf;
            acc.z += v0.z * wf;
            acc.w += v0.w * wf;
        }
        ((float4*)g_agg)[node * 32 + lane] = acc;

        int c = lane * 4;
        atomicAdd(&s_sum[c],     acc.x);
        atomicAdd(&s_sum[c + 1], acc.y);
        atomicAdd(&s_sum[c + 2], acc.z);
        atomicAdd(&s_sum[c + 3], acc.w);
        atomicAdd(&s_sq[c],      acc.x * acc.x);
        atomicAdd(&s_sq[c + 1],  acc.y * acc.y);
        atomicAdd(&s_sq[c + 2],  acc.z * acc.z);
        atomicAdd(&s_sq[c + 3],  acc.w * acc.w);
    }
    __syncthreads();
    if (tid < DD) {
        atomicAdd(&g_stats[soff + tid],      s_sum[tid]);
        atomicAdd(&g_stats[soff + DD + tid], s_sq[tid]);
    }
}

// ================= final BN + PReLU =================
__global__ void k_bn_out(const float* __restrict__ gamma,
                         const float* __restrict__ beta,
                         const float* __restrict__ aparam,
                         int soff, float* __restrict__ out) {
    int idx = blockIdx.x * 256 + threadIdx.x;
    if (idx >= NN * 32) return;
    int c = (idx & 31) * 4;
    float alpha = aparam[0];
    float4 v = ((const float4*)g_agg)[idx];
    float vv[4] = {v.x, v.y, v.z, v.w};
    float oo[4];
#pragma unroll
    for (int j = 0; j < 4; j++) {
        float mu  = g_stats[soff + c + j] * (1.f / NN);
        float var = g_stats[soff + DD + c + j] * (1.f / NN) - mu * mu;
        float rs  = rsqrtf(var + BN_EPS);
        float y = (vv[j] - mu) * rs * __ldg(&gamma[c + j]) + __ldg(&beta[c + j]);
        oo[j] = (y >= 0.f) ? y : alpha * y;
    }
    ((float4*)out)[idx] = make_float4(oo[0], oo[1], oo[2], oo[3]);
}

// ================= launch =================
extern "C" void kernel_launch(void* const* d_in, const int* in_sizes, int n_in,
                              void* d_out, int out_size) {
    const float* x      = (const float*)d_in[0];
    const int*   eidx   = (const int*)d_in[1];
    const float* W1     = (const float*)d_in[2];
    const float* b1     = (const float*)d_in[3];
    const float* gamma1 = (const float*)d_in[4];
    const float* beta1  = (const float*)d_in[5];
    const float* a1     = (const float*)d_in[6];
    const float* W2     = (const float*)d_in[7];
    const float* b2     = (const float*)d_in[8];
    const float* gamma2 = (const float*)d_in[9];
    const float* beta2  = (const float*)d_in[10];
    const float* a2     = (const float*)d_in[11];
    float* out = (float*)d_out;

    const int* src = eidx;
    const int* dst = eidx + NE;

    static bool s_init = false;
    static cudaStream_t s_side = nullptr;
    static cudaEvent_t ev_fork = nullptr, ev_join = nullptr;
    static void* p_deg = nullptr;
    static void* p_stats = nullptr;
    static unsigned short *p_w1h, *p_w1l, *p_w2h, *p_w2l;
    if (!s_init) {
        s_init = true;
        cudaGetSymbolAddress(&p_deg, g_deg);
        cudaGetSymbolAddress(&p_stats, g_stats);
        cudaGetSymbolAddress((void**)&p_w1h, g_w1h);
        cudaGetSymbolAddress((void**)&p_w1l, g_w1l);
        cudaGetSymbolAddress((void**)&p_w2h, g_w2h);
        cudaGetSymbolAddress((void**)&p_w2l, g_w2l);
        if (cudaStreamCreateWithFlags(&s_side, cudaStreamNonBlocking) == cudaSuccess) {
            if (cudaEventCreateWithFlags(&ev_fork, cudaEventDisableTiming) != cudaSuccess ||
                cudaEventCreateWithFlags(&ev_join, cudaEventDisableTiming) != cudaSuccess) {
                s_side = nullptr;
            }
        } else {
            s_side = nullptr;
        }
        cudaFuncSetAttribute(k_gemm_mma, cudaFuncAttributeMaxDynamicSharedMemorySize,
                             SMEM_MMA);
    }

    int nb_scan = (NN + 255) / 256;
    int nb_edge = (NE + 255) / 256;
    int nb_deg  = (NE / 4 + 255) / 256;
    int nb_gemm = (NN + 127) / 128;  // 391
    int nb_agg  = (NN + 7) / 8;
    int nb_elem = (NN * 32 + 255) / 256;

    cudaStream_t sp = s_side ? s_side : (cudaStream_t)0;

    if (s_side) {
        cudaEventRecord(ev_fork, 0);
        cudaStreamWaitEvent(s_side, ev_fork, 0);
    }

    // ---- preprocessing chain (side stream) ----
    cudaMemsetAsync(p_deg, 0, NN * sizeof(int), sp);
    k_deg<<<nb_deg, 256, 0, sp>>>(dst);
    k_scan1<<<nb_scan, 256, 0, sp>>>();
    k_scan2<<<1, 256, 0, sp>>>(nb_scan);
    k_scan3<<<nb_scan, 256, 0, sp>>>();
    k_csr<<<nb_edge, 256, 0, sp>>>(src, dst);

    // ---- main stream: W prepack + stats clear + GEMM-1 ----
    cudaMemsetAsync(p_stats, 0, 4 * DD * sizeof(float), 0);
    k_wprep<<<(2 * DD * DD + 255) / 256, 256>>>(W1, W2);
    k_gemm_mma<<<nb_gemm, 256, SMEM_MMA>>>(x, p_w1h, p_w1l,
                                           nullptr, nullptr, nullptr, -1, 0);

    if (s_side) {
        cudaEventRecord(ev_join, s_side);
        cudaStreamWaitEvent(0, ev_join, 0);
    }

    // ---- layer 1 aggregation ----
    k_agg<<<nb_agg, 256>>>(b1, 0);

    // ---- layer 2 (BN1+PReLU fused into GEMM X load) ----
    k_gemm_mma<<<nb_gemm, 256, SMEM_MMA>>>(nullptr, p_w2h, p_w2l,
                                           gamma1, beta1, a1, 0, 1);
    k_agg<<<nb_agg, 256>>>(b2, 2 * DD);

    // ---- final BN2 + PReLU -> output ----
    k_bn_out<<<nb_elem, 256>>>(gamma2, beta2, a2, 2 * DD, out);
}

// round 6
// speedup vs baseline: 1.5521x; 1.0550x over previous
#include <cuda_runtime.h>
#include <cuda_bf16.h>
#include <cstdint>

#define NN 50000
#define NE 800000
#define DD 128
#define BN_EPS 1e-5f
#define WSTRIDE 136                      // padded row stride (bf16 elems)
#define WTILE_BYTES (DD * WSTRIDE * 2)   // 34816 bytes per 128x128 bf16 tile

// ---- static device scratch ----
__device__ float g_h[NN * DD];
__device__ float g_agg[NN * DD];
__device__ int   g_deg[NN];
__device__ float g_dinv[NN];
__device__ int   g_rowstart[NN];
__device__ int   g_cursor[NN];
__device__ int   g_bsum[256];
__device__ int2  g_csre[NE];
__device__ float g_stats[4 * DD];
__device__ __align__(16) unsigned short g_w1h[DD * WSTRIDE];
__device__ __align__(16) unsigned short g_w1l[DD * WSTRIDE];
__device__ __align__(16) unsigned short g_w2h[DD * WSTRIDE];
__device__ __align__(16) unsigned short g_w2l[DD * WSTRIDE];

// ================= helpers =================
__device__ __forceinline__ uint32_t smem_u32(const void* p) {
    uint32_t a;
    asm("{ .reg .u64 t; cvta.to.shared.u64 t, %1; cvt.u32.u64 %0, t; }"
        : "=r"(a) : "l"(p));
    return a;
}
__device__ __forceinline__ void ldsm4(uint32_t& r0, uint32_t& r1,
                                      uint32_t& r2, uint32_t& r3, uint32_t addr) {
    asm volatile("ldmatrix.sync.aligned.m8n8.x4.shared.b16 {%0,%1,%2,%3}, [%4];"
                 : "=r"(r0), "=r"(r1), "=r"(r2), "=r"(r3) : "r"(addr));
}
__device__ __forceinline__ void mma16816(float* c, uint32_t a0, uint32_t a1,
                                         uint32_t a2, uint32_t a3,
                                         uint32_t b0, uint32_t b1) {
    asm volatile("mma.sync.aligned.m16n8k16.row.col.f32.bf16.bf16.f32 "
                 "{%0,%1,%2,%3}, {%4,%5,%6,%7}, {%8,%9}, {%0,%1,%2,%3};"
                 : "+f"(c[0]), "+f"(c[1]), "+f"(c[2]), "+f"(c[3])
                 : "r"(a0), "r"(a1), "r"(a2), "r"(a3), "r"(b0), "r"(b1));
}
__device__ __forceinline__ unsigned short bf_hi(float x) {
    __nv_bfloat16 b = __float2bfloat16(x);
    return *reinterpret_cast<unsigned short*>(&b);
}
__device__ __forceinline__ float bf_val(unsigned short u) {
    __nv_bfloat16 b = *reinterpret_cast<__nv_bfloat16*>(&u);
    return __bfloat162float(b);
}

// ================= graph preprocessing =================
__global__ void k_deg(const int* __restrict__ dst) {
    int t = blockIdx.x * 256 + threadIdx.x;
    if (t * 4 < NE) {
        int4 d = ((const int4*)dst)[t];
        atomicAdd(&g_deg[d.x], 1);
        atomicAdd(&g_deg[d.y], 1);
        atomicAdd(&g_deg[d.z], 1);
        atomicAdd(&g_deg[d.w], 1);
    }
}

__global__ void k_scan1() {
    __shared__ int wsum[8];
    int tid = threadIdx.x;
    int i = blockIdx.x * 256 + tid;
    int d0 = (i < NN) ? g_deg[i] : 0;
    int v = d0;
    int lane = tid & 31, wid = tid >> 5;
#pragma unroll
    for (int o = 1; o < 32; o <<= 1) {
        int n = __shfl_up_sync(0xffffffffu, v, o);
        if (lane >= o) v += n;
    }
    if (lane == 31) wsum[wid] = v;
    __syncthreads();
    if (wid == 0) {
        int s = (lane < 8) ? wsum[lane] : 0;
#pragma unroll
        for (int o = 1; o < 8; o <<= 1) {
            int n = __shfl_up_sync(0xffffffffu, s, o);
            if (lane >= o) s += n;
        }
        if (lane < 8) wsum[lane] = s;
    }
    __syncthreads();
    int off = (wid > 0) ? wsum[wid - 1] : 0;
    int incl = v + off;
    if (i < NN) {
        g_rowstart[i] = incl - d0;
        g_dinv[i] = rsqrtf((float)(d0 + 1));
    }
    if (tid == 255) g_bsum[blockIdx.x] = incl;
}

__global__ void k_scan2(int nb) {
    __shared__ int wsum[8];
    int tid = threadIdx.x;
    int d0 = (tid < nb) ? g_bsum[tid] : 0;
    int v = d0;
    int lane = tid & 31, wid = tid >> 5;
#pragma unroll
    for (int o = 1; o < 32; o <<= 1) {
        int n = __shfl_up_sync(0xffffffffu, v, o);
        if (lane >= o) v += n;
    }
    if (lane == 31) wsum[wid] = v;
    __syncthreads();
    if (wid == 0) {
        int s = (lane < 8) ? wsum[lane] : 0;
#pragma unroll
        for (int o = 1; o < 8; o <<= 1) {
            int n = __shfl_up_sync(0xffffffffu, s, o);
            if (lane >= o) s += n;
        }
        if (lane < 8) wsum[lane] = s;
    }
    __syncthreads();
    int off = (wid > 0) ? wsum[wid - 1] : 0;
    if (tid < nb) g_bsum[tid] = (v + off) - d0;
}

__global__ void k_scan3() {
    int i = blockIdx.x * 256 + threadIdx.x;
    if (i < NN) {
        int rs = g_rowstart[i] + g_bsum[blockIdx.x];
        g_rowstart[i] = rs;
        g_cursor[i] = rs;
    }
}

__global__ void k_csr(const int* __restrict__ src, const int* __restrict__ dst) {
    int e = blockIdx.x * 256 + threadIdx.x;
    if (e < NE) {
        int s = src[e], d = dst[e];
        int pos = atomicAdd(&g_cursor[d], 1);
        float w = g_dinv[s] * g_dinv[d];
        g_csre[pos] = make_int2(s, __float_as_int(w));
    }
}

// ================= W prepack: Wt[n][k] hi/lo, padded stride =================
__global__ void k_wprep(const float* __restrict__ W1, const float* __restrict__ W2) {
    int i = blockIdx.x * 256 + threadIdx.x;
    if (i >= 2 * DD * DD) return;
    int layer = i >> 14;
    int idx = i & (DD * DD - 1);
    int k = idx >> 7, n = idx & 127;
    float w = (layer ? W2 : W1)[idx];
    unsigned short h = bf_hi(w);
    unsigned short l = bf_hi(w - bf_val(h));
    int o = n * WSTRIDE + k;
    if (layer) { g_w2h[o] = h; g_w2l[o] = l; }
    else       { g_w1h[o] = h; g_w1l[o] = l; }
}

// ================= bf16 mma GEMM: 128-row tile, 3-term split =================
#define XH_OFF 0
#define XL_OFF WTILE_BYTES
#define WH_OFF (2 * WTILE_BYTES)
#define WL_OFF (3 * WTILE_BYTES)
#define SMEM_MMA (4 * WTILE_BYTES)

__global__ void __launch_bounds__(256) k_gemm_mma(
        const float* __restrict__ Xin,
        const unsigned short* __restrict__ Wh, const unsigned short* __restrict__ Wl,
        const float* __restrict__ gamma, const float* __restrict__ beta,
        const float* __restrict__ aparam, int bn_off, int use_agg) {
    extern __shared__ char sm[];
    __shared__ float s_scale[DD];
    __shared__ float s_shift[DD];

    int tid = threadIdx.x;
    int wid = tid >> 5, lane = tid & 31;
    int row0 = blockIdx.x * 128;
    const float* X = use_agg ? (const float*)g_agg : Xin;

    float alpha = 0.f;
    if (bn_off >= 0) {
        alpha = aparam[0];
        if (tid < DD) {
            float mu  = g_stats[bn_off + tid] * (1.f / NN);
            float var = g_stats[bn_off + DD + tid] * (1.f / NN) - mu * mu;
            float sc  = gamma[tid] * rsqrtf(var + BN_EPS);
            s_scale[tid] = sc;
            s_shift[tid] = beta[tid] - mu * sc;
        }
    }

    // copy prepacked W hi/lo (raw, padded layout preserved)
    {
        const float4* sh = (const float4*)Wh;
        const float4* sl = (const float4*)Wl;
        float4* dh = (float4*)(sm + WH_OFF);
        float4* dl = (float4*)(sm + WL_OFF);
#pragma unroll 4
        for (int i = tid; i < WTILE_BYTES / 16; i += 256) { dh[i] = sh[i]; dl[i] = sl[i]; }
    }
    __syncthreads();  // s_scale ready for X split

    // load X tile (optional BN+PReLU), split hi/lo into padded smem
    {
        const float4* X4 = (const float4*)X;
#pragma unroll 4
        for (int i = tid; i < 128 * 32; i += 256) {
            int r = i >> 5, c = i & 31;
            int gr = row0 + r;
            float4 v = make_float4(0.f, 0.f, 0.f, 0.f);
            if (gr < NN) v = X4[gr * 32 + c];
            if (bn_off >= 0) {
                int cc = c * 4;
                float y;
                y = v.x * s_scale[cc]     + s_shift[cc];     v.x = (y >= 0.f) ? y : alpha * y;
                y = v.y * s_scale[cc + 1] + s_shift[cc + 1]; v.y = (y >= 0.f) ? y : alpha * y;
                y = v.z * s_scale[cc + 2] + s_shift[cc + 2]; v.z = (y >= 0.f) ? y : alpha * y;
                y = v.w * s_scale[cc + 3] + s_shift[cc + 3]; v.w = (y >= 0.f) ? y : alpha * y;
            }
            unsigned short h0 = bf_hi(v.x), h1 = bf_hi(v.y), h2 = bf_hi(v.z), h3 = bf_hi(v.w);
            unsigned short l0 = bf_hi(v.x - bf_val(h0));
            unsigned short l1 = bf_hi(v.y - bf_val(h1));
            unsigned short l2 = bf_hi(v.z - bf_val(h2));
            unsigned short l3 = bf_hi(v.w - bf_val(h3));
            int o = r * (WSTRIDE * 2) + c * 8;
            *(uint2*)(sm + XH_OFF + o) = make_uint2((uint32_t)h0 | ((uint32_t)h1 << 16),
                                                    (uint32_t)h2 | ((uint32_t)h3 << 16));
            *(uint2*)(sm + XL_OFF + o) = make_uint2((uint32_t)l0 | ((uint32_t)l1 << 16),
                                                    (uint32_t)l2 | ((uint32_t)l3 << 16));
        }
    }
    __syncthreads();

    // fragment addresses
    int wrow0 = wid * 16;
    uint32_t base = smem_u32(sm);
    uint32_t a_h = base + XH_OFF + (wrow0 + (lane & 15)) * (WSTRIDE * 2) + (lane >> 4) * 16;
    uint32_t a_l = a_h + (XL_OFF - XH_OFF);
    // B x4 address: lanes 0-15 -> n-rows 0-7 (khalf 0/1), lanes 16-31 -> n-rows 8-15
    uint32_t b_h = base + WH_OFF + ((lane >> 4) * 8 + (lane & 7)) * (WSTRIDE * 2)
                 + ((lane >> 3) & 1) * 16;
    uint32_t b_l = b_h + (WL_OFF - WH_OFF);

    float acc[16][4];
#pragma unroll
    for (int nt = 0; nt < 16; nt++)
#pragma unroll
        for (int j = 0; j < 4; j++) acc[nt][j] = 0.f;

#pragma unroll 1
    for (int p = 0; p < 3; p++) {
        uint32_t aa = (p == 2) ? a_l : a_h;
        uint32_t bb = (p == 1) ? b_l : b_h;
#pragma unroll 1
        for (int k = 0; k < 8; k++) {
            uint32_t a0, a1, a2, a3;
            ldsm4(a0, a1, a2, a3, aa + k * 32);
#pragma unroll
            for (int ntp = 0; ntp < 8; ntp++) {
                uint32_t b0, b1, b2, b3;  // (nt=2ntp k0,k1), (nt=2ntp+1 k0,k1)
                ldsm4(b0, b1, b2, b3, bb + k * 32 + ntp * 16 * (WSTRIDE * 2));
                mma16816(acc[2 * ntp],     a0, a1, a2, a3, b0, b1);
                mma16816(acc[2 * ntp + 1], a0, a1, a2, a3, b2, b3);
            }
        }
    }

    // epilogue
    int g = lane >> 2, t = lane & 3;
    int r1 = row0 + wrow0 + g;
    int r2 = r1 + 8;
#pragma unroll
    for (int nt = 0; nt < 16; nt++) {
        int col = nt * 8 + t * 2;
        if (r1 < NN)
            *(float2*)(g_h + (size_t)r1 * DD + col) = make_float2(acc[nt][0], acc[nt][1]);
        if (r2 < NN)
            *(float2*)(g_h + (size_t)r2 * DD + col) = make_float2(acc[nt][2], acc[nt][3]);
    }
}

// ================= CSR aggregation (+ fused BN stats) =================
__global__ void k_agg(const float* __restrict__ bias, int soff) {
    __shared__ float s_sum[DD];
    __shared__ float s_sq[DD];
    int tid = threadIdx.x;
    if (tid < DD) { s_sum[tid] = 0.f; s_sq[tid] = 0.f; }
    __syncthreads();

    int node = blockIdx.x * 8 + (tid >> 5);
    int lane = tid & 31;
    if (node < NN) {
        const float4* h4 = (const float4*)g_h;
        float di = g_dinv[node];
        float w0 = di * di;
        float4 acc = h4[node * 32 + lane];
        float4 bv = ((const float4*)bias)[lane];
        acc.x = acc.x * w0 + bv.x;
        acc.y = acc.y * w0 + bv.y;
        acc.z = acc.z * w0 + bv.z;
        acc.w = acc.w * w0 + bv.w;

        int base = g_rowstart[node];
        int cnt  = g_deg[node];
        const int2* ep = g_csre + base;
        int j = 0;
#pragma unroll 1
        for (; j + 8 <= cnt; j += 8) {
            int2 e[8];
#pragma unroll
            for (int u = 0; u < 8; u++) e[u] = __ldg(ep + j + u);
            float4 v[8];
#pragma unroll
            for (int u = 0; u < 8; u++) v[u] = h4[e[u].x * 32 + lane];
#pragma unroll
            for (int u = 0; u < 8; u++) {
                float wf = __int_as_float(e[u].y);
                acc.x += v[u].x * wf;
                acc.y += v[u].y * wf;
                acc.z += v[u].z * wf;
                acc.w += v[u].w * wf;
            }
        }
        for (; j < cnt; j++) {
            int2 e0 = __ldg(ep + j);
            float4 v0 = h4[e0.x * 32 + lane];
            float wf = __int_as_float(e0.y);
            acc.x += v0.x * wf;
            acc.y += v0.y * wf;
            acc.z += v0.z * wf;
            acc.w += v0.w * wf;
        }
        ((float4*)g_agg)[node * 32 + lane] = acc;

        int c = lane * 4;
        atomicAdd(&s_sum[c],     acc.x);
        atomicAdd(&s_sum[c + 1], acc.y);
        atomicAdd(&s_sum[c + 2], acc.z);
        atomicAdd(&s_sum[c + 3], acc.w);
        atomicAdd(&s_sq[c],      acc.x * acc.x);
        atomicAdd(&s_sq[c + 1],  acc.y * acc.y);
        atomicAdd(&s_sq[c + 2],  acc.z * acc.z);
        atomicAdd(&s_sq[c + 3],  acc.w * acc.w);
    }
    __syncthreads();
    if (tid < DD) {
        atomicAdd(&g_stats[soff + tid],      s_sum[tid]);
        atomicAdd(&g_stats[soff + DD + tid], s_sq[tid]);
    }
}

// ================= final BN + PReLU =================
__global__ void k_bn_out(const float* __restrict__ gamma,
                         const float* __restrict__ beta,
                         const float* __restrict__ aparam,
                         int soff, float* __restrict__ out) {
    int idx = blockIdx.x * 256 + threadIdx.x;
    if (idx >= NN * 32) return;
    int c = (idx & 31) * 4;
    float alpha = aparam[0];
    float4 v = ((const float4*)g_agg)[idx];
    float vv[4] = {v.x, v.y, v.z, v.w};
    float oo[4];
#pragma unroll
    for (int j = 0; j < 4; j++) {
        float mu  = g_stats[soff + c + j] * (1.f / NN);
        float var = g_stats[soff + DD + c + j] * (1.f / NN) - mu * mu;
        float rs  = rsqrtf(var + BN_EPS);
        float y = (vv[j] - mu) * rs * __ldg(&gamma[c + j]) + __ldg(&beta[c + j]);
        oo[j] = (y >= 0.f) ? y : alpha * y;
    }
    ((float4*)out)[idx] = make_float4(oo[0], oo[1], oo[2], oo[3]);
}

// ================= launch =================
extern "C" void kernel_launch(void* const* d_in, const int* in_sizes, int n_in,
                              void* d_out, int out_size) {
    const float* x      = (const float*)d_in[0];
    const int*   eidx   = (const int*)d_in[1];
    const float* W1     = (const float*)d_in[2];
    const float* b1     = (const float*)d_in[3];
    const float* gamma1 = (const float*)d_in[4];
    const float* beta1  = (const float*)d_in[5];
    const float* a1     = (const float*)d_in[6];
    const float* W2     = (const float*)d_in[7];
    const float* b2     = (const float*)d_in[8];
    const float* gamma2 = (const float*)d_in[9];
    const float* beta2  = (const float*)d_in[10];
    const float* a2     = (const float*)d_in[11];
    float* out = (float*)d_out;

    const int* src = eidx;
    const int* dst = eidx + NE;

    static bool s_init = false;
    static cudaStream_t s_side = nullptr;
    static cudaEvent_t ev_fork = nullptr, ev_join = nullptr;
    static void* p_deg = nullptr;
    static void* p_stats = nullptr;
    static unsigned short *p_w1h, *p_w1l, *p_w2h, *p_w2l;
    if (!s_init) {
        s_init = true;
        cudaGetSymbolAddress(&p_deg, g_deg);
        cudaGetSymbolAddress(&p_stats, g_stats);
        cudaGetSymbolAddress((void**)&p_w1h, g_w1h);
        cudaGetSymbolAddress((void**)&p_w1l, g_w1l);
        cudaGetSymbolAddress((void**)&p_w2h, g_w2h);
        cudaGetSymbolAddress((void**)&p_w2l, g_w2l);
        if (cudaStreamCreateWithFlags(&s_side, cudaStreamNonBlocking) == cudaSuccess) {
            if (cudaEventCreateWithFlags(&ev_fork, cudaEventDisableTiming) != cudaSuccess ||
                cudaEventCreateWithFlags(&ev_join, cudaEventDisableTiming) != cudaSuccess) {
                s_side = nullptr;
            }
        } else {
            s_side = nullptr;
        }
        cudaFuncSetAttribute(k_gemm_mma, cudaFuncAttributeMaxDynamicSharedMemorySize,
                             SMEM_MMA);
    }

    int nb_scan = (NN + 255) / 256;
    int nb_edge = (NE + 255) / 256;
    int nb_deg  = (NE / 4 + 255) / 256;
    int nb_gemm = (NN + 127) / 128;
    int nb_agg  = (NN + 7) / 8;
    int nb_elem = (NN * 32 + 255) / 256;

    cudaStream_t sp = s_side ? s_side : (cudaStream_t)0;

    if (s_side) {
        cudaEventRecord(ev_fork, 0);
        cudaStreamWaitEvent(s_side, ev_fork, 0);
    }

    // side stream part 1 (launch-ordered so k_gemm_mma is the 4th kernel -> ncu target)
    cudaMemsetAsync(p_deg, 0, NN * sizeof(int), sp);
    k_deg<<<nb_deg, 256, 0, sp>>>(dst);
    k_scan1<<<nb_scan, 256, 0, sp>>>();

    // main stream: stats clear + W prepack + GEMM-1
    cudaMemsetAsync(p_stats, 0, 4 * DD * sizeof(float), 0);
    k_wprep<<<(2 * DD * DD + 255) / 256, 256>>>(W1, W2);
    k_gemm_mma<<<nb_gemm, 256, SMEM_MMA>>>(x, p_w1h, p_w1l,
                                           nullptr, nullptr, nullptr, -1, 0);

    // side stream part 2
    k_scan2<<<1, 256, 0, sp>>>(nb_scan);
    k_scan3<<<nb_scan, 256, 0, sp>>>();
    k_csr<<<nb_edge, 256, 0, sp>>>(src, dst);

    if (s_side) {
        cudaEventRecord(ev_join, s_side);
        cudaStreamWaitEvent(0, ev_join, 0);
    }

    // layer 1 aggregation
    k_agg<<<nb_agg, 256>>>(b1, 0);

    // layer 2 (BN1+PReLU fused into GEMM X load)
    k_gemm_mma<<<nb_gemm, 256, SMEM_MMA>>>(nullptr, p_w2h, p_w2l,
                                           gamma1, beta1, a1, 0, 1);
    k_agg<<<nb_agg, 256>>>(b2, 2 * DD);

    // final BN2 + PReLU -> output
    k_bn_out<<<nb_elem, 256>>>(gamma2, beta2, a2, 2 * DD, out);
}